// round 2
// baseline (speedup 1.0000x reference)
#include <cuda_runtime.h>
#include <math.h>

#define NB 8
#define NT 8192
#define ND 2048
#define NROWS (NB * NT)
#define KSEL 2048   // NT * 0.25

// Scratch (no allocations allowed; device globals are the sanctioned path)
__device__ float  d_Dst[NROWS];
__device__ float  d_Dch[NROWS];
__device__ double d_ma;

// ---------------------------------------------------------------------------
// Kernel 1: per-row squared-norm reductions. Warp-per-row: 8 rows per CTA,
// 16 independent float4 loads per input per lane -> deep MLP, no smem, no
// __syncthreads. This kernel reads the full 1.07 GB and IS the runtime.
// Deterministic fixed-order reduction.
// ---------------------------------------------------------------------------
__global__ void __launch_bounds__(256) row_reduce_kernel(
    const float4* __restrict__ a, const float4* __restrict__ p)
{
    const int warp = threadIdx.x >> 5;
    const int lane = threadIdx.x & 31;
    const int row  = blockIdx.x * 8 + warp;
    const size_t base = (size_t)row * (ND / 4);

    float s_st = 0.0f, s_ch = 0.0f;
#pragma unroll
    for (int j = 0; j < 16; ++j) {
        const size_t idx = base + lane + 32 * j;
        float4 av = __ldg(&a[idx]);
        float4 pv = __ldg(&p[idx]);
        s_st += av.x * av.x + av.y * av.y + av.z * av.z + av.w * av.w;
        float dx = av.x - pv.x, dy = av.y - pv.y;
        float dz = av.z - pv.z, dw = av.w - pv.w;
        s_ch += dx * dx + dy * dy + dz * dz + dw * dw;
    }

#pragma unroll
    for (int off = 16; off > 0; off >>= 1) {
        s_st += __shfl_down_sync(0xFFFFFFFFu, s_st, off);
        s_ch += __shfl_down_sync(0xFFFFFFFFu, s_ch, off);
    }

    if (lane == 0) {
        const float invd = 1.0f / (float)ND;
        d_Dst[row] = s_st * invd;
        d_Dch[row] = s_ch * invd;
    }
}

// ---------------------------------------------------------------------------
// Kernel 2: global mean of D_st (fp64, fixed order -> deterministic).
// ---------------------------------------------------------------------------
__global__ void __launch_bounds__(1024) mean_kernel()
{
    const int t = threadIdx.x;
    double s = 0.0;
    for (int i = t; i < NROWS; i += 1024) s += (double)d_Dst[i];
#pragma unroll
    for (int off = 16; off > 0; off >>= 1)
        s += __shfl_down_sync(0xFFFFFFFFu, s, off);
    __shared__ double ws[32];
    if ((t & 31) == 0) ws[t >> 5] = s;
    __syncthreads();
    if (t == 0) {
        double tot = 0.0;
#pragma unroll
        for (int i = 0; i < 32; ++i) tot += ws[i];
        d_ma = tot / (double)NROWS;
    }
}

// ---------------------------------------------------------------------------
// Kernel 3: gate computation across the whole chip (fp64 for ordering
// fidelity: order-statistic gaps near the k-th largest g are ~4e-6, so fp32
// gate math risks flipping the top-k mask vs the reference). 64 CTAs spread
// the DFMA/exp work over the SMs instead of serializing it on 8.
// ---------------------------------------------------------------------------
__global__ void __launch_bounds__(1024) gate_kernel(
    const float* __restrict__ oce, const float* __restrict__ mcu,
    const float* __restrict__ bce, const float* __restrict__ bcu,
    float* __restrict__ out)
{
    const double ma      = d_ma;
    const double log_oce = log((double)oce[0] + 1e-10);
    const double m       = (double)mcu[0];
    const double xce     = (double)bce[0];
    const double xcu     = (double)bcu[0];
    // numerically stable softplus
    const double bce_p = fmax(xce, 0.0) + log1p(exp(-fabs(xce)));
    const double bcu_p = fmax(xcu, 0.0) + log1p(exp(-fabs(xcu)));

    const int idx = blockIdx.x * 1024 + threadIdx.x;  // grid covers NROWS exactly
    const double dst = (double)d_Dst[idx];
    const double dch = (double)d_Dch[idx];
    const double CE = dst - (dch - log_oce);
    const double CU = dst - m * ma;
    const double sce = 1.0 / (1.0 + exp(-bce_p * CE));
    const double scu = 1.0 / (1.0 + exp(-bcu_p * CU));
    out[idx] = (float)(sce + scu - sce * scu);
}

// ---------------------------------------------------------------------------
// Kernel 4: exact per-batch top-k via 4-pass radix select on the float bit
// pattern (g in (0,1) -> uint order == float order). One CTA per batch.
// Tie handling mirrors jax.lax.top_k (lower index wins).
// ---------------------------------------------------------------------------
__global__ void __launch_bounds__(1024) select_kernel(
    const float* __restrict__ g, float* __restrict__ out)
{
    __shared__ unsigned s_u[NT];
    __shared__ int hist[256];
    __shared__ unsigned s_pref;
    __shared__ int s_remk, s_ce;

    const int b = blockIdx.x;
    const int t = threadIdx.x;

    for (int i = t; i < NT; i += 1024)
        s_u[i] = __float_as_uint(g[b * NT + i]);

    if (t == 0) { s_pref = 0u; s_remk = KSEL; s_ce = 0; }
    __syncthreads();

    for (int shift = 24; shift >= 0; shift -= 8) {
        if (t < 256) hist[t] = 0;
        __syncthreads();
        const unsigned mask = (shift == 24) ? 0u : (0xFFFFFFFFu << (shift + 8));
        const unsigned pref = s_pref;
        for (int i = t; i < NT; i += 1024) {
            const unsigned u = s_u[i];
            if ((u & mask) == pref)
                atomicAdd(&hist[(u >> shift) & 0xFF], 1);
        }
        __syncthreads();
        if (t == 0) {
            int cum = 0, bin = 0;
            const int remk = s_remk;
            for (int bn = 255; bn >= 0; --bn) {
                const int c = hist[bn];
                if (cum + c >= remk) { bin = bn; if (shift == 0) s_ce = c; break; }
                cum += c;
            }
            s_pref |= (unsigned)bin << shift;
            s_remk = remk - cum;   // still needed among elements in chosen bin
        }
        __syncthreads();
    }

    const unsigned thresh = s_pref;   // exact bit pattern of k-th largest
    const int need_eq = s_remk;       // equal-to-threshold elements to accept
    const int c_eq = s_ce;            // equal-to-threshold elements present

    for (int i = t; i < NT; i += 1024) {
        const unsigned u = s_u[i];
        float mval;
        if (u > thresh)      mval = 1.0f;
        else if (u < thresh) mval = 0.0f;
        else if (c_eq == need_eq) mval = 1.0f;          // no over-tie (common)
        else {
            // rare exact fp32 tie at threshold: lower index wins
            int r = 0;
            for (int j = 0; j < i; ++j) if (s_u[j] == thresh) ++r;
            mval = (r < need_eq) ? 1.0f : 0.0f;
        }
        out[NROWS + b * NT + i] = mval;
    }
}

// ---------------------------------------------------------------------------
extern "C" void kernel_launch(void* const* d_in, const int* in_sizes, int n_in,
                              void* d_out, int out_size)
{
    const float4* a = (const float4*)d_in[0];   // actual_residual   [8,8192,2048] f32
    const float4* p = (const float4*)d_in[1];   // predicted_residual[8,8192,2048] f32
    const float* oce = (const float*)d_in[2];
    const float* mcu = (const float*)d_in[3];
    const float* bce = (const float*)d_in[4];
    const float* bcu = (const float*)d_in[5];
    float* out = (float*)d_out;                  // [2, 8, 8192]: g then binary mask

    row_reduce_kernel<<<NROWS / 8, 256>>>(a, p);
    mean_kernel<<<1, 1024>>>();
    gate_kernel<<<NROWS / 1024, 1024>>>(oce, mcu, bce, bcu, out);
    select_kernel<<<NB, 1024>>>(out, out);
}

// round 3
// speedup vs baseline: 1.0301x; 1.0301x over previous
#include <cuda_runtime.h>
#include <math.h>

#define NB 8
#define NT 8192
#define ND 2048
#define NROWS (NB * NT)
#define KSEL 2048   // NT * 0.25

// Scratch (no allocations allowed; device globals are the sanctioned path)
__device__ float  d_Dst[NROWS];
__device__ float  d_Dch[NROWS];
__device__ double d_ma;

// ---------------------------------------------------------------------------
// Kernel 1: per-row squared-norm reductions. Warp-per-row, 16 independent
// float4 loads per input per lane -> deep MLP, no smem, no barriers.
// Reads the full 1.07 GB at the LTS cap -> this kernel IS the runtime.
// ---------------------------------------------------------------------------
__global__ void __launch_bounds__(256) row_reduce_kernel(
    const float4* __restrict__ a, const float4* __restrict__ p)
{
    const int warp = threadIdx.x >> 5;
    const int lane = threadIdx.x & 31;
    const int row  = blockIdx.x * 8 + warp;
    const size_t base = (size_t)row * (ND / 4);

    float s_st = 0.0f, s_ch = 0.0f;
#pragma unroll
    for (int j = 0; j < 16; ++j) {
        const size_t idx = base + lane + 32 * j;
        float4 av = __ldg(&a[idx]);
        float4 pv = __ldg(&p[idx]);
        s_st += av.x * av.x + av.y * av.y + av.z * av.z + av.w * av.w;
        float dx = av.x - pv.x, dy = av.y - pv.y;
        float dz = av.z - pv.z, dw = av.w - pv.w;
        s_ch += dx * dx + dy * dy + dz * dz + dw * dw;
    }

#pragma unroll
    for (int off = 16; off > 0; off >>= 1) {
        s_st += __shfl_down_sync(0xFFFFFFFFu, s_st, off);
        s_ch += __shfl_down_sync(0xFFFFFFFFu, s_ch, off);
    }

    if (lane == 0) {
        const float invd = 1.0f / (float)ND;
        d_Dst[row] = s_st * invd;
        d_Dch[row] = s_ch * invd;
    }
}

// ---------------------------------------------------------------------------
// Kernel 2: global mean of D_st (fp64, fixed order -> deterministic).
// 4 independent accumulators to break the DADD latency chain.
// ---------------------------------------------------------------------------
__global__ void __launch_bounds__(1024) mean_kernel()
{
    const int t = threadIdx.x;
    double s0 = 0.0, s1 = 0.0, s2 = 0.0, s3 = 0.0;
    for (int i = t; i < NROWS; i += 4096) {
        s0 += (double)d_Dst[i];
        s1 += (double)d_Dst[i + 1024];
        s2 += (double)d_Dst[i + 2048];
        s3 += (double)d_Dst[i + 3072];
    }
    double s = (s0 + s1) + (s2 + s3);
#pragma unroll
    for (int off = 16; off > 0; off >>= 1)
        s += __shfl_down_sync(0xFFFFFFFFu, s, off);
    __shared__ double ws[32];
    if ((t & 31) == 0) ws[t >> 5] = s;
    __syncthreads();
    if (t == 0) {
        double tot = 0.0;
#pragma unroll
        for (int i = 0; i < 32; ++i) tot += ws[i];
        d_ma = tot / (double)NROWS;
    }
}

// ---------------------------------------------------------------------------
// Kernel 3: gate computation across the whole chip. fp64 for ordering
// fidelity (order-statistic gaps near the k-th largest g are ~4e-6; a single
// ordering flip vs the reference's top-k costs ~1e-2 rel_err on the mask).
// ---------------------------------------------------------------------------
__global__ void __launch_bounds__(1024) gate_kernel(
    const float* __restrict__ oce, const float* __restrict__ mcu,
    const float* __restrict__ bce, const float* __restrict__ bcu,
    float* __restrict__ out)
{
    const double ma      = d_ma;
    const double log_oce = log((double)oce[0] + 1e-10);
    const double m       = (double)mcu[0];
    const double xce     = (double)bce[0];
    const double xcu     = (double)bcu[0];
    // numerically stable softplus
    const double bce_p = fmax(xce, 0.0) + log1p(exp(-fabs(xce)));
    const double bcu_p = fmax(xcu, 0.0) + log1p(exp(-fabs(xcu)));

    const int idx = blockIdx.x * 1024 + threadIdx.x;  // grid covers NROWS exactly
    const double dst = (double)d_Dst[idx];
    const double dch = (double)d_Dch[idx];
    const double CE = dst - (dch - log_oce);
    const double CU = dst - m * ma;
    const double sce = 1.0 / (1.0 + exp(-bce_p * CE));
    const double scu = 1.0 / (1.0 + exp(-bcu_p * CU));
    out[idx] = (float)(sce + scu - sce * scu);
}

// ---------------------------------------------------------------------------
// Kernel 4: exact per-batch top-k via 4-pass radix select on the float bit
// pattern (g in (0,1) -> uint order == float order). One CTA per batch.
//
// R2 ncu showed 26.8us here at issue=13%: g values cluster into few bins, so
// cross-warp atomicAdd to the same smem address serialized at 32 cyc/warp,
// plus a serial 256-bin scan on thread 0. Fix: warp-aggregated counting
// (__match_any_sync -> one plain STS per distinct bin per warp) into
// warp-PRIVATE histogram rows (no atomics at all), and a shuffle-based
// parallel suffix scan of the 256 bins. g is re-read from L1/L2 each pass
// (keeps static smem at 33KB < 48KB).
// Tie handling mirrors jax.lax.top_k (lower index wins).
// ---------------------------------------------------------------------------
__global__ void __launch_bounds__(1024) select_kernel(
    const float* __restrict__ g, float* __restrict__ out)
{
    __shared__ int hist[32 * 256];   // [warp][bin], 32KB
    __shared__ int s_bincnt[256];
    __shared__ int warp_tot[8];
    __shared__ unsigned s_pref;
    __shared__ int s_remk, s_ce;

    const int b    = blockIdx.x;
    const int t    = threadIdx.x;
    const int warp = t >> 5;
    const int lane = t & 31;
    const float* gb = g + b * NT;

    if (t == 0) { s_pref = 0u; s_remk = KSEL; s_ce = 0; }
    __syncthreads();

    for (int shift = 24; shift >= 0; shift -= 8) {
        // snapshot state (written at end of previous pass, fenced by barrier)
        const unsigned pref = s_pref;
        const int remk = s_remk;
        const unsigned msk = (shift == 24) ? 0u : (0xFFFFFFFFu << (shift + 8));

        // zero warp-private histograms
#pragma unroll
        for (int i = 0; i < 8; ++i) hist[t + i * 1024] = 0;
        __syncthreads();

        // warp-aggregated counting: no atomics, no cross-warp traffic
        int* myhist = hist + warp * 256;
#pragma unroll
        for (int it = 0; it < 8; ++it) {
            const unsigned u = __float_as_uint(__ldg(&gb[t + it * 1024]));
            const bool ok = ((u & msk) == pref);
            const int bin = (u >> shift) & 0xFF;
            const unsigned active = __ballot_sync(0xFFFFFFFFu, ok);
            if (ok) {
                const unsigned peers = __match_any_sync(active, bin);
                if (lane == (__ffs(peers) - 1))
                    myhist[bin] += __popc(peers);   // leader only: plain LDS/STS
            }
        }
        __syncthreads();

        // sum bin t across the 32 warp rows (threads 0..255)
        int v = 0;
        if (t < 256) {
#pragma unroll
            for (int w = 0; w < 32; ++w) v += hist[w * 256 + t];
            s_bincnt[255 - t] = v;   // store reversed for suffix-scan read below
        }
        __syncthreads();

        // suffix scan from the top bin: thread t handles bin r = 255 - t.
        // inclusive shuffle scan over t ascending == cumulative count of bins >= r.
        int x = 0;
        if (t < 256) {
            x = s_bincnt[t];         // = count of bin (255 - t)
#pragma unroll
            for (int off = 1; off < 32; off <<= 1) {
                const int y = __shfl_up_sync(0xFFFFFFFFu, x, off);
                if (lane >= off) x += y;
            }
            if (lane == 31) warp_tot[warp] = x;
        }
        __syncthreads();
        if (t < 256) {
            int offset = 0;
            for (int w = 0; w < warp; ++w) offset += warp_tot[w];
            const int cum  = x + offset;            // count of bins >= r
            const int vv   = s_bincnt[t];           // count of bin r
            const int prev = cum - vv;              // count of bins  > r
            if (prev < remk && cum >= remk) {       // exactly one thread wins
                const int r = 255 - t;
                s_pref = pref | ((unsigned)r << shift);
                s_remk = remk - prev;
                if (shift == 0) s_ce = vv;
            }
        }
        __syncthreads();
    }

    const unsigned thresh = s_pref;   // exact bit pattern of k-th largest
    const int need_eq = s_remk;       // equal-to-threshold elements to accept
    const int c_eq = s_ce;            // equal-to-threshold elements present

    // write binary mask (second output half)
#pragma unroll
    for (int it = 0; it < 8; ++it) {
        const int i = t + it * 1024;
        const unsigned u = __float_as_uint(__ldg(&gb[i]));
        float mval;
        if (u > thresh)      mval = 1.0f;
        else if (u < thresh) mval = 0.0f;
        else if (c_eq == need_eq) mval = 1.0f;          // no over-tie (common)
        else {
            // rare exact fp32 tie at threshold: lower index wins
            int r = 0;
            for (int j = 0; j < i; ++j)
                if (__float_as_uint(__ldg(&gb[j])) == thresh) ++r;
            mval = (r < need_eq) ? 1.0f : 0.0f;
        }
        out[NROWS + b * NT + i] = mval;
    }
}

// ---------------------------------------------------------------------------
extern "C" void kernel_launch(void* const* d_in, const int* in_sizes, int n_in,
                              void* d_out, int out_size)
{
    const float4* a = (const float4*)d_in[0];   // actual_residual   [8,8192,2048] f32
    const float4* p = (const float4*)d_in[1];   // predicted_residual[8,8192,2048] f32
    const float* oce = (const float*)d_in[2];
    const float* mcu = (const float*)d_in[3];
    const float* bce = (const float*)d_in[4];
    const float* bcu = (const float*)d_in[5];
    float* out = (float*)d_out;                  // [2, 8, 8192]: g then binary mask

    row_reduce_kernel<<<NROWS / 8, 256>>>(a, p);
    mean_kernel<<<1, 1024>>>();
    gate_kernel<<<NROWS / 1024, 1024>>>(oce, mcu, bce, bcu, out);
    select_kernel<<<NB, 1024>>>(out, out);
}